// round 5
// baseline (speedup 1.0000x reference)
#include <cuda_runtime.h>
#include <cstdint>

#define BB 2048
#define ASTR 68                 // A row stride in words (64 + 4 pad)
#define BSTR 36
#define ABYTES (128 * ASTR * 4) // 34816 per buffer

// smem byte offsets
#define OFF_A    0
#define OFF_B    (2 * ABYTES)          // 69632
#define OFF_PSM  (OFF_B + 9216)        // 78848
#define OFF_CTXP (OFF_PSM + 512)       // 79360
#define OFF_CTXA (OFF_CTXP + 2048)     // 81408
#define OFF_S    (OFF_CTXA + 256)      // 81664
#define OFF_PRE  (OFF_S + 128)
#define OFF_V    (OFF_PRE + 128)
#define OFF_GH   (OFF_V + 128)
#define OFF_GIE  (OFF_GH + 384)
#define OFF_EMB  (OFF_GIE + 384)
#define OFF_RED  (OFF_EMB + 64)
#define OFF_LSUM (OFF_RED + 32)
#define SMEM_SZ  (OFF_LSUM + 16)       // ~82.9 KB

__device__ __forceinline__ uint32_t smem_u32(const void* p) {
    uint32_t a;
    asm("{ .reg .u64 t; cvta.to.shared.u64 t, %1; cvt.u32.u64 %0, t; }" : "=r"(a) : "l"(p));
    return a;
}
__device__ __forceinline__ uint32_t f2tf32(float x) {
    uint32_t r; asm("cvt.rna.tf32.f32 %0, %1;" : "=r"(r) : "f"(x)); return r;
}
__device__ __forceinline__ float tanh_ap(float x) {
    float y; asm("tanh.approx.f32 %0, %1;" : "=f"(y) : "f"(x)); return y;
}
__device__ __forceinline__ float sigm(float x) { return 1.0f / (1.0f + __expf(-x)); }

__device__ __forceinline__ void cpasync16(uint32_t dst, const void* src) {
    asm volatile("cp.async.cg.shared.global [%0], [%1], 16;" :: "r"(dst), "l"(src) : "memory");
}
__device__ __forceinline__ void cp_commit() {
    asm volatile("cp.async.commit_group;" ::: "memory");
}
__device__ __forceinline__ void cp_wait0() {
    asm volatile("cp.async.wait_group 0;" ::: "memory");
}

__device__ __forceinline__ void mma_tf32(float* d, const uint32_t* a, const uint32_t* bb) {
    asm volatile(
        "mma.sync.aligned.m16n8k8.row.col.f32.tf32.tf32.f32 "
        "{%0,%1,%2,%3}, {%4,%5,%6,%7}, {%8,%9}, {%0,%1,%2,%3};"
        : "+f"(d[0]), "+f"(d[1]), "+f"(d[2]), "+f"(d[3])
        : "r"(a[0]), "r"(a[1]), "r"(a[2]), "r"(a[3]), "r"(bb[0]), "r"(bb[1]));
}

__global__ __launch_bounds__(256) void decoder_pipe_kernel(
    const float* __restrict__ dec_in, const float* __restrict__ s_in,
    const float* __restrict__ enc,    const float* __restrict__ W_attn,
    const float* __restrict__ b_attn, const float* __restrict__ v_attn,
    const float* __restrict__ W_emb,  const float* __restrict__ b_emb,
    const float* __restrict__ W_ih,   const float* __restrict__ W_hh,
    const float* __restrict__ b_ih,   const float* __restrict__ b_hh,
    const float* __restrict__ W_fc,   const float* __restrict__ b_fc,
    float* __restrict__ out, int write_h)
{
    extern __shared__ __align__(16) unsigned char sm[];
    float*    Asf    = (float*)(sm + OFF_A);        // [2][128*ASTR] fp32
    uint32_t* Bs     = (uint32_t*)(sm + OFF_B);
    float*    psm    = (float*)(sm + OFF_PSM);
    float*    ctxp   = (float*)(sm + OFF_CTXP);     // [8][64]
    float*    ctxa   = (float*)(sm + OFF_CTXA);
    float*    s_sm   = (float*)(sm + OFF_S);
    float*    pre_sm = (float*)(sm + OFF_PRE);
    float*    v_sm2  = (float*)(sm + OFF_V);
    float*    gh_sm  = (float*)(sm + OFF_GH);
    float*    gie_sm = (float*)(sm + OFF_GIE);
    float*    emb_sm = (float*)(sm + OFF_EMB);
    float*    red    = (float*)(sm + OFF_RED);
    float*    lsum   = (float*)(sm + OFF_LSUM);

    const int t    = threadIdx.x;
    const int b    = blockIdx.x;
    const int lane = t & 31;
    const int w    = t >> 5;
    const int qid  = lane >> 2;
    const int qtr  = lane & 3;
    const int sg   = t >> 3;
    const int si   = t & 7;
    const uint32_t su = smem_u32(sm);

    // staging geometry: thread covers 8 half-rows, 16 B each
    const int   hrow  = sg;                 // base half-row (advances by 32)
    const float* gbase = enc + (size_t)b * 64 + (size_t)(hrow >> 1) * (BB * 64)
                         + (hrow & 1) * 32 + si * 4;
    const uint32_t sbase = su + OFF_A + ((hrow >> 1) * ASTR + (hrow & 1) * 32 + si * 4) * 4;

    // ---- prologue: kick off chunk 0 stream immediately ----
    {
        const float* g = gbase;
        uint32_t s = sbase;
        #pragma unroll
        for (int it = 0; it < 8; ++it) {
            cpasync16(s, g);
            g += 16 * (BB * 64);            // 16 rows forward
            s += 16 * ASTR * 4;
        }
        cp_commit();
    }

    // ---- init / precompute (overlaps chunk-0 stream) ----
    if (t < 32) s_sm[t] = s_in[b * 32 + t];
    if (t < 16) {
        float e = W_emb[t] * dec_in[b] + b_emb[t];
        emb_sm[t] = e > 0.f ? e : 0.f;
    }
    for (int idx = t; idx < 2048; idx += 256) {
        int j = idx >> 6, k = idx & 63;
        Bs[k * BSTR + j] = f2tf32(W_attn[j * 96 + 32 + k]);
    }
    __syncthreads();

    if (t < 32) {
        float a = b_attn[t];
        #pragma unroll
        for (int m = 0; m < 32; ++m) a += W_attn[t * 96 + m] * s_sm[m];
        pre_sm[t] = a;
        v_sm2[t]  = v_attn[t];
    } else if (t < 128) {
        int g = t - 32;
        float a = b_hh[g];
        #pragma unroll
        for (int m = 0; m < 32; ++m) a += W_hh[g * 32 + m] * s_sm[m];
        gh_sm[g] = a;
    } else if (t < 224) {
        int g = t - 128;
        float a = b_ih[g];
        #pragma unroll
        for (int m = 0; m < 16; ++m) a += W_ih[g * 80 + m] * emb_sm[m];
        gie_sm[g] = a;
    }
    __syncthreads();

    // B fragments in registers (constant over chunks)
    uint32_t Br[4][8][2];
    #pragma unroll
    for (int nt = 0; nt < 4; ++nt)
        #pragma unroll
        for (int ks = 0; ks < 8; ++ks) {
            Br[nt][ks][0] = Bs[(8 * ks + qtr) * BSTR + 8 * nt + qid];
            Br[nt][ks][1] = Bs[(8 * ks + 4 + qtr) * BSTR + 8 * nt + qid];
        }
    float preR[4][2], vR[4][2];
    #pragma unroll
    for (int nt = 0; nt < 4; ++nt) {
        int c = nt * 8 + 2 * qtr;
        preR[nt][0] = pre_sm[c];  preR[nt][1] = pre_sm[c + 1];
        vR[nt][0]   = v_sm2[c];   vR[nt][1]   = v_sm2[c + 1];
    }

    const int m0 = w * 16;
    float cacc0 = 0.f, cacc1 = 0.f, l_acc = 0.f;

    // ---------------- pipelined chunk loop ----------------
    for (int ch = 0; ch < 4; ++ch) {
        cp_wait0();          // chunk ch landed (per-thread)
        __syncthreads();     // visible to all; prior iter's ctx reads done

        // prefetch chunk ch+1 into the other buffer
        if (ch < 3) {
            const float* g = gbase + (size_t)(ch + 1) * 128 * (BB * 64);
            uint32_t s = sbase + ((ch + 1) & 1) * ABYTES;
            #pragma unroll
            for (int it = 0; it < 8; ++it) {
                cpasync16(s, g);
                g += 16 * (BB * 64);
                s += 16 * ASTR * 4;
            }
            cp_commit();
        }

        const float* A = Asf + (ch & 1) * (128 * ASTR);
        const float* aptr = A + (m0 + qid) * ASTR + qtr;

        // MMA: D[16m x 32n] per warp, K=64
        float D[4][4];
        #pragma unroll
        for (int nt = 0; nt < 4; ++nt)
            #pragma unroll
            for (int i = 0; i < 4; ++i) D[nt][i] = 0.f;

        #pragma unroll
        for (int ks = 0; ks < 8; ++ks) {
            uint32_t a[4];
            a[0] = f2tf32(aptr[8 * ks]);
            a[1] = f2tf32(aptr[8 * ASTR + 8 * ks]);
            a[2] = f2tf32(aptr[8 * ks + 4]);
            a[3] = f2tf32(aptr[8 * ASTR + 8 * ks + 4]);
            #pragma unroll
            for (int nt = 0; nt < 4; ++nt) mma_tf32(D[nt], a, Br[nt][ks]);
        }

        // logits (registers) -> quad reduce -> psm (intra-warp only)
        float pl0 = 0.f, pl1 = 0.f;
        #pragma unroll
        for (int nt = 0; nt < 4; ++nt) {
            pl0 += vR[nt][0] * tanh_ap(D[nt][0] + preR[nt][0]);
            pl0 += vR[nt][1] * tanh_ap(D[nt][1] + preR[nt][1]);
            pl1 += vR[nt][0] * tanh_ap(D[nt][2] + preR[nt][0]);
            pl1 += vR[nt][1] * tanh_ap(D[nt][3] + preR[nt][1]);
        }
        pl0 += __shfl_xor_sync(0xffffffffu, pl0, 1);
        pl0 += __shfl_xor_sync(0xffffffffu, pl0, 2);
        pl1 += __shfl_xor_sync(0xffffffffu, pl1, 1);
        pl1 += __shfl_xor_sync(0xffffffffu, pl1, 2);
        if (qtr == 0) {
            float p0 = __expf(pl0);   // |logit| <= ||v||_1 ~ 1.3, exp safe
            float p1 = __expf(pl1);
            psm[m0 + qid]     = p0;
            psm[m0 + 8 + qid] = p1;
            l_acc += p0 + p1;
        }
        __syncwarp();

        // ctx: warp sweeps its 16 rows, lanes cover h = 2*lane, 2*lane+1
        #pragma unroll
        for (int rr = 0; rr < 16; ++rr) {
            int row = m0 + rr;
            float ps = psm[row];
            float2 e2 = *(const float2*)&A[row * ASTR + 2 * lane];
            cacc0 += ps * e2.x;
            cacc1 += ps * e2.y;
        }
    }

    // ---------------- reductions ----------------
    ctxp[w * 64 + 2 * lane]     = cacc0;
    ctxp[w * 64 + 2 * lane + 1] = cacc1;
    {
        float ws = l_acc;
        #pragma unroll
        for (int off = 16; off > 0; off >>= 1)
            ws += __shfl_xor_sync(0xffffffffu, ws, off);
        if (lane == 0) red[w] = ws;
    }
    __syncthreads();
    if (t == 0)
        lsum[0] = red[0] + red[1] + red[2] + red[3] +
                  red[4] + red[5] + red[6] + red[7];
    __syncthreads();
    if (t < 64) {
        float c = 0.f;
        #pragma unroll
        for (int ww = 0; ww < 8; ++ww) c += ctxp[ww * 64 + t];
        ctxa[t] = c / lsum[0];
    }
    __syncthreads();

    // ---------------- GRU + fc (warp 0) ----------------
    if (w == 0) {
        int j = lane;
        float gir = gie_sm[j], giz = gie_sm[32 + j], gin = gie_sm[64 + j];
        const float* wr = W_ih + j        * 80 + 16;
        const float* wz = W_ih + (32 + j) * 80 + 16;
        const float* wn = W_ih + (64 + j) * 80 + 16;
        #pragma unroll 8
        for (int k2 = 0; k2 < 64; ++k2) {
            float c = ctxa[k2];
            gir += wr[k2] * c;
            giz += wz[k2] * c;
            gin += wn[k2] * c;
        }
        float r = sigm(gir + gh_sm[j]);
        float z = sigm(giz + gh_sm[32 + j]);
        float n = tanhf(gin + r * gh_sm[64 + j]);
        float h = (1.f - z) * n + z * s_sm[j];
        if (write_h) out[BB + b * 32 + j] = h;

        float contrib = h * W_fc[j]
                      + ctxa[2 * j]     * W_fc[32 + 2 * j]
                      + ctxa[2 * j + 1] * W_fc[33 + 2 * j];
        if (j < 16) contrib += emb_sm[j] * W_fc[96 + j];
        #pragma unroll
        for (int off = 16; off > 0; off >>= 1)
            contrib += __shfl_xor_sync(0xffffffffu, contrib, off);
        if (j == 0) out[b] = contrib + b_fc[0];
    }
}

extern "C" void kernel_launch(void* const* d_in, const int* in_sizes, int n_in,
                              void* d_out, int out_size) {
    const float* dec_in = (const float*)d_in[0];
    const float* s_in   = (const float*)d_in[1];
    const float* enc    = (const float*)d_in[2];
    const float* W_attn = (const float*)d_in[3];
    const float* b_attn = (const float*)d_in[4];
    const float* v_attn = (const float*)d_in[5];
    const float* W_emb  = (const float*)d_in[6];
    const float* b_emb  = (const float*)d_in[7];
    const float* W_ih   = (const float*)d_in[8];
    const float* W_hh   = (const float*)d_in[9];
    const float* b_ih   = (const float*)d_in[10];
    const float* b_hh   = (const float*)d_in[11];
    const float* W_fc   = (const float*)d_in[12];
    const float* b_fc   = (const float*)d_in[13];

    cudaFuncSetAttribute(decoder_pipe_kernel,
                         cudaFuncAttributeMaxDynamicSharedMemorySize, SMEM_SZ);
    int write_h = (out_size >= BB * 33) ? 1 : 0;
    decoder_pipe_kernel<<<BB, 256, SMEM_SZ>>>(dec_in, s_in, enc, W_attn, b_attn, v_attn,
                                              W_emb, b_emb, W_ih, W_hh, b_ih, b_hh,
                                              W_fc, b_fc, (float*)d_out, write_h);
}

// round 7
// speedup vs baseline: 1.3865x; 1.3865x over previous
#include <cuda_runtime.h>
#include <cstdint>

#define BB 2048
#define SC 64                   // rows per chunk
#define NCH 8
#define ASTR 68                 // A row stride in words (64 + 4 pad)
#define BSTR 36
#define ABYTES (SC * ASTR * 4)  // 17408 per buffer

// smem byte offsets (all dynamic)
#define OFF_A    0
#define OFF_B    (2 * ABYTES)           // 34816
#define OFF_PART (OFF_B + 9216)         // 44032  [2][64]
#define OFF_PSM  (OFF_PART + 512)       // 44544  [64]
#define OFF_CTXP (OFF_PSM + 256)        // 44800  [8][64]
#define OFF_CTXA (OFF_CTXP + 2048)      // 46848
#define OFF_S    (OFF_CTXA + 256)
#define OFF_PRE  (OFF_S + 128)
#define OFF_V    (OFF_PRE + 128)
#define OFF_GH   (OFF_V + 128)
#define OFF_GIE  (OFF_GH + 384)
#define OFF_EMB  (OFF_GIE + 384)
#define OFF_RED  (OFF_EMB + 64)
#define OFF_LSUM (OFF_RED + 32)
#define SMEM_SZ  (OFF_LSUM + 16)        // ~48.4 KB

__device__ __forceinline__ uint32_t smem_u32(const void* p) {
    uint32_t a;
    asm("{ .reg .u64 t; cvta.to.shared.u64 t, %1; cvt.u32.u64 %0, t; }" : "=r"(a) : "l"(p));
    return a;
}
__device__ __forceinline__ uint32_t f2tf32(float x) {
    uint32_t r; asm("cvt.rna.tf32.f32 %0, %1;" : "=r"(r) : "f"(x)); return r;
}
__device__ __forceinline__ float tanh_ap(float x) {
    float y; asm("tanh.approx.f32 %0, %1;" : "=f"(y) : "f"(x)); return y;
}
__device__ __forceinline__ float sigm(float x) { return 1.0f / (1.0f + __expf(-x)); }

__device__ __forceinline__ void cpasync16(uint32_t dst, const void* src) {
    asm volatile("cp.async.cg.shared.global [%0], [%1], 16;" :: "r"(dst), "l"(src) : "memory");
}
__device__ __forceinline__ void cp_commit() {
    asm volatile("cp.async.commit_group;" ::: "memory");
}
__device__ __forceinline__ void cp_wait0() {
    asm volatile("cp.async.wait_group 0;" ::: "memory");
}
__device__ __forceinline__ void mma_tf32(float* d, const uint32_t* a, const uint32_t* bb) {
    asm volatile(
        "mma.sync.aligned.m16n8k8.row.col.f32.tf32.tf32.f32 "
        "{%0,%1,%2,%3}, {%4,%5,%6,%7}, {%8,%9}, {%0,%1,%2,%3};"
        : "+f"(d[0]), "+f"(d[1]), "+f"(d[2]), "+f"(d[3])
        : "r"(a[0]), "r"(a[1]), "r"(a[2]), "r"(a[3]), "r"(bb[0]), "r"(bb[1]));
}

__global__ __launch_bounds__(256, 3) void decoder_pipe3_kernel(
    const float* __restrict__ dec_in, const float* __restrict__ s_in,
    const float* __restrict__ enc,    const float* __restrict__ W_attn,
    const float* __restrict__ b_attn, const float* __restrict__ v_attn,
    const float* __restrict__ W_emb,  const float* __restrict__ b_emb,
    const float* __restrict__ W_ih,   const float* __restrict__ W_hh,
    const float* __restrict__ b_ih,   const float* __restrict__ b_hh,
    const float* __restrict__ W_fc,   const float* __restrict__ b_fc,
    float* __restrict__ out, int write_h)
{
    extern __shared__ __align__(16) unsigned char sm[];
    float*    Asf    = (float*)(sm + OFF_A);
    uint32_t* Bs     = (uint32_t*)(sm + OFF_B);
    float*    part   = (float*)(sm + OFF_PART);
    float*    psm    = (float*)(sm + OFF_PSM);
    float*    ctxp   = (float*)(sm + OFF_CTXP);
    float*    ctxa   = (float*)(sm + OFF_CTXA);
    float*    s_sm   = (float*)(sm + OFF_S);
    float*    pre_sm = (float*)(sm + OFF_PRE);
    float*    v_sm2  = (float*)(sm + OFF_V);
    float*    gh_sm  = (float*)(sm + OFF_GH);
    float*    gie_sm = (float*)(sm + OFF_GIE);
    float*    emb_sm = (float*)(sm + OFF_EMB);
    float*    red    = (float*)(sm + OFF_RED);
    float*    lsum   = (float*)(sm + OFF_LSUM);

    const int t    = threadIdx.x;
    const int b    = blockIdx.x;
    const int lane = t & 31;
    const int w    = t >> 5;
    const int qid  = lane >> 2;
    const int qtr  = lane & 3;
    const uint32_t su = smem_u32(sm);

    // staging map: thread covers rows rowg+16*it (it<4), 16-B segment seg
    const int rowg = t >> 4;            // 0..15
    const int seg  = t & 15;            // 0..15
    const float* gbase = enc + ((size_t)rowg * BB + b) * 64 + seg * 4;
    const uint32_t sbase = su + OFF_A + (rowg * ASTR + seg * 4) * 4;
    const size_t gstep = (size_t)16 * BB * 64;   // 16 rows

    // ---- prologue: chunk 0 in flight immediately ----
    {
        const float* g = gbase;
        uint32_t s = sbase;
        #pragma unroll
        for (int it = 0; it < 4; ++it) {
            cpasync16(s, g);
            g += gstep;
            s += 16 * ASTR * 4;
        }
        cp_commit();
    }

    // ---- init / precompute (overlaps chunk-0 stream) ----
    if (t < 32) s_sm[t] = s_in[b * 32 + t];
    if (t < 16) {
        float e = W_emb[t] * dec_in[b] + b_emb[t];
        emb_sm[t] = e > 0.f ? e : 0.f;
    }
    for (int idx = t; idx < 2048; idx += 256) {
        int j = idx >> 6, k = idx & 63;
        Bs[k * BSTR + j] = f2tf32(W_attn[j * 96 + 32 + k]);
    }
    __syncthreads();

    if (t < 32) {
        float a = b_attn[t];
        #pragma unroll
        for (int m = 0; m < 32; ++m) a += W_attn[t * 96 + m] * s_sm[m];
        pre_sm[t] = a;
        v_sm2[t]  = v_attn[t];
    } else if (t < 128) {
        int g = t - 32;
        float a = b_hh[g];
        #pragma unroll
        for (int m = 0; m < 32; ++m) a += W_hh[g * 32 + m] * s_sm[m];
        gh_sm[g] = a;
    } else if (t < 224) {
        int g = t - 128;
        float a = b_ih[g];
        #pragma unroll
        for (int m = 0; m < 16; ++m) a += W_ih[g * 80 + m] * emb_sm[m];
        gie_sm[g] = a;
    }
    __syncthreads();

    // warp tiling: rows m0..m0+15, cols [n0, n0+16)
    const int m0 = (w & 3) * 16;
    const int nhalf = w >> 2;           // 0 or 1
    const int nt0 = nhalf * 2;

    uint32_t Br[2][8][2];
    #pragma unroll
    for (int i = 0; i < 2; ++i)
        #pragma unroll
        for (int ks = 0; ks < 8; ++ks) {
            int col = 8 * (nt0 + i) + qid;
            Br[i][ks][0] = Bs[(8 * ks + qtr)     * BSTR + col];
            Br[i][ks][1] = Bs[(8 * ks + 4 + qtr) * BSTR + col];
        }
    float preR[2][2], vR[2][2];
    #pragma unroll
    for (int i = 0; i < 2; ++i) {
        int c = (nt0 + i) * 8 + 2 * qtr;
        preR[i][0] = pre_sm[c];  preR[i][1] = pre_sm[c + 1];
        vR[i][0]   = v_sm2[c];   vR[i][1]   = v_sm2[c + 1];
    }

    float cacc0 = 0.f, cacc1 = 0.f, l_acc = 0.f;

    // ---------------- pipelined chunk loop ----------------
    for (int ch = 0; ch < NCH; ++ch) {
        cp_wait0();
        __syncthreads();               // chunk ch visible; prior ctx reads done

        if (ch < NCH - 1) {
            const float* g = gbase + (size_t)(ch + 1) * SC * (BB * 64);
            uint32_t s = sbase + ((ch + 1) & 1) * ABYTES;
            #pragma unroll
            for (int it = 0; it < 4; ++it) {
                cpasync16(s, g);
                g += gstep;
                s += 16 * ASTR * 4;
            }
            cp_commit();
        }

        const float* A = Asf + (ch & 1) * (SC * ASTR);
        const float* aptr = A + (m0 + qid) * ASTR + qtr;

        float D[2][4];
        #pragma unroll
        for (int i = 0; i < 2; ++i)
            #pragma unroll
            for (int k = 0; k < 4; ++k) D[i][k] = 0.f;

        #pragma unroll
        for (int ks = 0; ks < 8; ++ks) {
            uint32_t a[4];
            a[0] = f2tf32(aptr[8 * ks]);
            a[1] = f2tf32(aptr[8 * ASTR + 8 * ks]);
            a[2] = f2tf32(aptr[8 * ks + 4]);
            a[3] = f2tf32(aptr[8 * ASTR + 8 * ks + 4]);
            mma_tf32(D[0], a, Br[0][ks]);
            mma_tf32(D[1], a, Br[1][ks]);
        }

        // half-logit partials over this warp's 16 cols
        float pl0 = 0.f, pl1 = 0.f;
        #pragma unroll
        for (int i = 0; i < 2; ++i) {
            pl0 += vR[i][0] * tanh_ap(D[i][0] + preR[i][0]);
            pl0 += vR[i][1] * tanh_ap(D[i][1] + preR[i][1]);
            pl1 += vR[i][0] * tanh_ap(D[i][2] + preR[i][0]);
            pl1 += vR[i][1] * tanh_ap(D[i][3] + preR[i][1]);
        }
        pl0 += __shfl_xor_sync(0xffffffffu, pl0, 1);
        pl0 += __shfl_xor_sync(0xffffffffu, pl0, 2);
        pl1 += __shfl_xor_sync(0xffffffffu, pl1, 1);
        pl1 += __shfl_xor_sync(0xffffffffu, pl1, 2);
        if (qtr == 0) {
            part[nhalf * 64 + m0 + qid]     = pl0;
            part[nhalf * 64 + m0 + 8 + qid] = pl1;
        }
        __syncthreads();

        if (t < 64) {
            float p = __expf(part[t] + part[64 + t]);   // |logit| <= ~1.3, safe
            psm[t] = p;
            l_acc += p;
        }
        __syncthreads();

        // ctx: warp sweeps rows w*8..w*8+7, lanes h = 2*lane, 2*lane+1
        #pragma unroll
        for (int rr = 0; rr < 8; ++rr) {
            int row = w * 8 + rr;
            float ps = psm[row];
            float2 e2 = *(const float2*)&A[row * ASTR + 2 * lane];
            cacc0 += ps * e2.x;
            cacc1 += ps * e2.y;
        }
    }

    // ---------------- reductions ----------------
    ctxp[w * 64 + 2 * lane]     = cacc0;
    ctxp[w * 64 + 2 * lane + 1] = cacc1;
    if (t < 64) {
        float ws = l_acc;
        #pragma unroll
        for (int off = 16; off > 0; off >>= 1)
            ws += __shfl_xor_sync(0xffffffffu, ws, off);
        if (lane == 0) red[w] = ws;
    }
    __syncthreads();
    if (t == 0) lsum[0] = red[0] + red[1];
    __syncthreads();
    if (t < 64) {
        float c = 0.f;
        #pragma unroll
        for (int ww = 0; ww < 8; ++ww) c += ctxp[ww * 64 + t];
        ctxa[t] = c / lsum[0];
    }
    __syncthreads();

    // ---------------- GRU + fc (warp 0) ----------------
    if (w == 0) {
        int j = lane;
        float gir = gie_sm[j], giz = gie_sm[32 + j], gin = gie_sm[64 + j];
        const float* wr = W_ih + j        * 80 + 16;
        const float* wz = W_ih + (32 + j) * 80 + 16;
        const float* wn = W_ih + (64 + j) * 80 + 16;
        #pragma unroll 8
        for (int k2 = 0; k2 < 64; ++k2) {
            float c = ctxa[k2];
            gir += wr[k2] * c;
            giz += wz[k2] * c;
            gin += wn[k2] * c;
        }
        float r = sigm(gir + gh_sm[j]);
        float z = sigm(giz + gh_sm[32 + j]);
        float n = tanhf(gin + r * gh_sm[64 + j]);
        float h = (1.f - z) * n + z * s_sm[j];
        if (write_h) out[BB + b * 32 + j] = h;

        float contrib = h * W_fc[j]
                      + ctxa[2 * j]     * W_fc[32 + 2 * j]
                      + ctxa[2 * j + 1] * W_fc[33 + 2 * j];
        if (j < 16) contrib += emb_sm[j] * W_fc[96 + j];
        #pragma unroll
        for (int off = 16; off > 0; off >>= 1)
            contrib += __shfl_xor_sync(0xffffffffu, contrib, off);
        if (j == 0) out[b] = contrib + b_fc[0];
    }
}

extern "C" void kernel_launch(void* const* d_in, const int* in_sizes, int n_in,
                              void* d_out, int out_size) {
    const float* dec_in = (const float*)d_in[0];
    const float* s_in   = (const float*)d_in[1];
    const float* enc    = (const float*)d_in[2];
    const float* W_attn = (const float*)d_in[3];
    const float* b_attn = (const float*)d_in[4];
    const float* v_attn = (const float*)d_in[5];
    const float* W_emb  = (const float*)d_in[6];
    const float* b_emb  = (const float*)d_in[7];
    const float* W_ih   = (const float*)d_in[8];
    const float* W_hh   = (const float*)d_in[9];
    const float* b_ih   = (const float*)d_in[10];
    const float* b_hh   = (const float*)d_in[11];
    const float* W_fc   = (const float*)d_in[12];
    const float* b_fc   = (const float*)d_in[13];

    cudaFuncSetAttribute(decoder_pipe3_kernel,
                         cudaFuncAttributeMaxDynamicSharedMemorySize, SMEM_SZ);
    int write_h = (out_size >= BB * 33) ? 1 : 0;
    decoder_pipe3_kernel<<<BB, 256, SMEM_SZ>>>(dec_in, s_in, enc, W_attn, b_attn, v_attn,
                                               W_emb, b_emb, W_ih, W_hh, b_ih, b_hh,
                                               W_fc, b_fc, (float*)d_out, write_h);
}

// round 9
// speedup vs baseline: 1.3886x; 1.0015x over previous
#include <cuda_runtime.h>
#include <cstdint>

#define BB 2048
#define SC 64                   // rows per chunk
#define NCH 8
#define ASTR 68                 // A row stride in words (64 + 4 pad)
#define BSTR 36
#define ABYTES (SC * ASTR * 4)  // 17408 per buffer
#define NBUF 3

// smem byte offsets (all dynamic)
#define OFF_A    0
#define OFF_B    (NBUF * ABYTES)        // 52224
#define OFF_PART (OFF_B + 9216)         // 61440  [2][64]
#define OFF_CTXP (OFF_PART + 512)       // 61952  [8][64]
#define OFF_CTXA (OFF_CTXP + 2048)      // 64000
#define OFF_S    (OFF_CTXA + 256)
#define OFF_PRE  (OFF_S + 128)
#define OFF_V    (OFF_PRE + 128)
#define OFF_GH   (OFF_V + 128)
#define OFF_GIE  (OFF_GH + 384)
#define OFF_EMB  (OFF_GIE + 384)
#define OFF_RED  (OFF_EMB + 64)
#define OFF_LSUM (OFF_RED + 32)
#define SMEM_SZ  (OFF_LSUM + 16)        // ~64 KB

__device__ __forceinline__ uint32_t smem_u32(const void* p) {
    uint32_t a;
    asm("{ .reg .u64 t; cvta.to.shared.u64 t, %1; cvt.u32.u64 %0, t; }" : "=r"(a) : "l"(p));
    return a;
}
__device__ __forceinline__ uint32_t f2tf32(float x) {
    uint32_t r; asm("cvt.rna.tf32.f32 %0, %1;" : "=r"(r) : "f"(x)); return r;
}
__device__ __forceinline__ float tanh_ap(float x) {
    float y; asm("tanh.approx.f32 %0, %1;" : "=f"(y) : "f"(x)); return y;
}
__device__ __forceinline__ float sigm(float x) { return 1.0f / (1.0f + __expf(-x)); }

__device__ __forceinline__ void cpasync16(uint32_t dst, const void* src) {
    asm volatile("cp.async.cg.shared.global [%0], [%1], 16;" :: "r"(dst), "l"(src) : "memory");
}
__device__ __forceinline__ void cp_commit() {
    asm volatile("cp.async.commit_group;" ::: "memory");
}
__device__ __forceinline__ void cp_wait0() {
    asm volatile("cp.async.wait_group 0;" ::: "memory");
}
__device__ __forceinline__ void cp_wait1() {
    asm volatile("cp.async.wait_group 1;" ::: "memory");
}
__device__ __forceinline__ void barpair(int id) {
    asm volatile("bar.sync %0, 64;" :: "r"(id) : "memory");
}
__device__ __forceinline__ void mma_tf32(float* d, const uint32_t* a, const uint32_t* bb) {
    asm volatile(
        "mma.sync.aligned.m16n8k8.row.col.f32.tf32.tf32.f32 "
        "{%0,%1,%2,%3}, {%4,%5,%6,%7}, {%8,%9}, {%0,%1,%2,%3};"
        : "+f"(d[0]), "+f"(d[1]), "+f"(d[2]), "+f"(d[3])
        : "r"(a[0]), "r"(a[1]), "r"(a[2]), "r"(a[3]), "r"(bb[0]), "r"(bb[1]));
}

__global__ __launch_bounds__(256, 3) void decoder_deep_kernel(
    const float* __restrict__ dec_in, const float* __restrict__ s_in,
    const float* __restrict__ enc,    const float* __restrict__ W_attn,
    const float* __restrict__ b_attn, const float* __restrict__ v_attn,
    const float* __restrict__ W_emb,  const float* __restrict__ b_emb,
    const float* __restrict__ W_ih,   const float* __restrict__ W_hh,
    const float* __restrict__ b_ih,   const float* __restrict__ b_hh,
    const float* __restrict__ W_fc,   const float* __restrict__ b_fc,
    float* __restrict__ out, int write_h)
{
    extern __shared__ __align__(16) unsigned char sm[];
    float*    Asf    = (float*)(sm + OFF_A);
    uint32_t* Bs     = (uint32_t*)(sm + OFF_B);
    float*    part   = (float*)(sm + OFF_PART);
    float*    ctxp   = (float*)(sm + OFF_CTXP);
    float*    ctxa   = (float*)(sm + OFF_CTXA);
    float*    s_sm   = (float*)(sm + OFF_S);
    float*    pre_sm = (float*)(sm + OFF_PRE);
    float*    v_sm2  = (float*)(sm + OFF_V);
    float*    gh_sm  = (float*)(sm + OFF_GH);
    float*    gie_sm = (float*)(sm + OFF_GIE);
    float*    emb_sm = (float*)(sm + OFF_EMB);
    float*    red    = (float*)(sm + OFF_RED);
    float*    lsum   = (float*)(sm + OFF_LSUM);

    const int t    = threadIdx.x;
    const int b    = blockIdx.x;
    const int lane = t & 31;
    const int w    = t >> 5;
    const int qid  = lane >> 2;
    const int qtr  = lane & 3;
    const uint32_t su = smem_u32(sm);

    // staging map: thread covers rows rowg+16*it (it<4), 16-B segment seg
    const int rowg = t >> 4;            // 0..15
    const int seg  = t & 15;            // 0..15
    const float* gbase = enc + ((size_t)rowg * BB + b) * 64 + seg * 4;
    const uint32_t sbase = su + OFF_A + (rowg * ASTR + seg * 4) * 4;
    const size_t gstep = (size_t)16 * BB * 64;   // 16 rows

    // ---- prologue: chunks 0 and 1 in flight ----
    #pragma unroll
    for (int c0 = 0; c0 < 2; ++c0) {
        const float* g = gbase + (size_t)c0 * SC * (BB * 64);
        uint32_t s = sbase + c0 * ABYTES;
        #pragma unroll
        for (int it = 0; it < 4; ++it) {
            cpasync16(s, g);
            g += gstep;
            s += 16 * ASTR * 4;
        }
        cp_commit();
    }

    // ---- init / precompute (overlaps streams) ----
    if (t < 32) s_sm[t] = s_in[b * 32 + t];
    if (t < 16) {
        float e = W_emb[t] * dec_in[b] + b_emb[t];
        emb_sm[t] = e > 0.f ? e : 0.f;
    }
    for (int idx = t; idx < 2048; idx += 256) {
        int j = idx >> 6, k = idx & 63;
        Bs[k * BSTR + j] = f2tf32(W_attn[j * 96 + 32 + k]);
    }
    __syncthreads();

    if (t < 32) {
        float a = b_attn[t];
        #pragma unroll
        for (int m = 0; m < 32; ++m) a += W_attn[t * 96 + m] * s_sm[m];
        pre_sm[t] = a;
        v_sm2[t]  = v_attn[t];
    } else if (t < 128) {
        int g = t - 32;
        float a = b_hh[g];
        #pragma unroll
        for (int m = 0; m < 32; ++m) a += W_hh[g * 32 + m] * s_sm[m];
        gh_sm[g] = a;
    } else if (t < 224) {
        int g = t - 128;
        float a = b_ih[g];
        #pragma unroll
        for (int m = 0; m < 16; ++m) a += W_ih[g * 80 + m] * emb_sm[m];
        gie_sm[g] = a;
    }
    __syncthreads();

    // warp tiling: rows m0..m0+15, cols [nhalf*16, nhalf*16+16)
    const int m0 = (w & 3) * 16;
    const int nhalf = w >> 2;           // 0 or 1
    const int nt0 = nhalf * 2;
    const int barid = 1 + (w & 3);
    const int ctxrow0 = m0 + nhalf * 8; // this warp's 8 ctx/exp rows

    uint32_t Br[2][8][2];
    #pragma unroll
    for (int i = 0; i < 2; ++i)
        #pragma unroll
        for (int ks = 0; ks < 8; ++ks) {
            int col = 8 * (nt0 + i) + qid;
            Br[i][ks][0] = Bs[(8 * ks + qtr)     * BSTR + col];
            Br[i][ks][1] = Bs[(8 * ks + 4 + qtr) * BSTR + col];
        }
    float preR[2][2], vR[2][2];
    #pragma unroll
    for (int i = 0; i < 2; ++i) {
        int c = (nt0 + i) * 8 + 2 * qtr;
        preR[i][0] = pre_sm[c];  preR[i][1] = pre_sm[c + 1];
        vR[i][0]   = v_sm2[c];   vR[i][1]   = v_sm2[c + 1];
    }

    float cacc0 = 0.f, cacc1 = 0.f, l_acc = 0.f;

    // ---------------- pipelined chunk loop (depth 2 ahead) ----------------
    for (int ch = 0; ch < NCH; ++ch) {
        if (ch == NCH - 1) cp_wait0(); else cp_wait1();   // chunk ch landed
        __syncthreads();   // visible to all; reads of buffer (ch+2)%3 (chunk ch-1) done

        if (ch + 2 < NCH) {
            const float* g = gbase + (size_t)(ch + 2) * SC * (BB * 64);
            uint32_t s = sbase + ((ch + 2) % NBUF) * ABYTES;
            #pragma unroll
            for (int it = 0; it < 4; ++it) {
                cpasync16(s, g);
                g += gstep;
                s += 16 * ASTR * 4;
            }
            cp_commit();
        }

        const float* A = Asf + (ch % NBUF) * (SC * ASTR);
        const float* aptr = A + (m0 + qid) * ASTR + qtr;

        float D[2][4];
        #pragma unroll
        for (int i = 0; i < 2; ++i)
            #pragma unroll
            for (int k = 0; k < 4; ++k) D[i][k] = 0.f;

        #pragma unroll
        for (int ks = 0; ks < 8; ++ks) {
            uint32_t a[4];
            a[0] = f2tf32(aptr[8 * ks]);
            a[1] = f2tf32(aptr[8 * ASTR + 8 * ks]);
            a[2] = f2tf32(aptr[8 * ks + 4]);
            a[3] = f2tf32(aptr[8 * ASTR + 8 * ks + 4]);
            mma_tf32(D[0], a, Br[0][ks]);
            mma_tf32(D[1], a, Br[1][ks]);
        }

        // half-logit partials over this warp's 16 cols
        float pl0 = 0.f, pl1 = 0.f;
        #pragma unroll
        for (int i = 0; i < 2; ++i) {
            pl0 += vR[i][0] * tanh_ap(D[i][0] + preR[i][0]);
            pl0 += vR[i][1] * tanh_ap(D[i][1] + preR[i][1]);
            pl1 += vR[i][0] * tanh_ap(D[i][2] + preR[i][0]);
            pl1 += vR[i][1] * tanh_ap(D[i][3] + preR[i][1]);
        }
        pl0 += __shfl_xor_sync(0xffffffffu, pl0, 1);
        pl0 += __shfl_xor_sync(0xffffffffu, pl0, 2);
        pl1 += __shfl_xor_sync(0xffffffffu, pl1, 1);
        pl1 += __shfl_xor_sync(0xffffffffu, pl1, 2);
        if (qtr == 0) {
            part[nhalf * 64 + m0 + qid]     = pl0;
            part[nhalf * 64 + m0 + 8 + qid] = pl1;
        }
        barpair(barid);    // pair (w, w+4) exchanged half-logits

        // exp once per row (lanes 0..7), broadcast via shuffle into ctx loop
        float pexp = 0.f;
        if (lane < 8) {
            int row = ctxrow0 + lane;
            pexp = __expf(part[row] + part[64 + row]);   // |logit| <= ~1.3, safe
            l_acc += pexp;
        }
        #pragma unroll
        for (int rr = 0; rr < 8; ++rr) {
            float ps = __shfl_sync(0xffffffffu, pexp, rr);
            float2 e2 = *(const float2*)&A[(ctxrow0 + rr) * ASTR + 2 * lane];
            cacc0 += ps * e2.x;
            cacc1 += ps * e2.y;
        }
    }

    // ---------------- reductions ----------------
    ctxp[w * 64 + 2 * lane]     = cacc0;
    ctxp[w * 64 + 2 * lane + 1] = cacc1;
    {
        float ws = l_acc;   // only lanes 0..7 nonzero
        #pragma unroll
        for (int off = 16; off > 0; off >>= 1)
            ws += __shfl_xor_sync(0xffffffffu, ws, off);
        if (lane == 0) red[w] = ws;
    }
    __syncthreads();
    if (t == 0)
        lsum[0] = red[0] + red[1] + red[2] + red[3] +
                  red[4] + red[5] + red[6] + red[7];
    __syncthreads();
    if (t < 64) {
        float c = 0.f;
        #pragma unroll
        for (int ww = 0; ww < 8; ++ww) c += ctxp[ww * 64 + t];
        ctxa[t] = c / lsum[0];
    }
    __syncthreads();

    // ---------------- GRU + fc (warp 0) ----------------
    if (w == 0) {
        int j = lane;
        float gir = gie_sm[j], giz = gie_sm[32 + j], gin = gie_sm[64 + j];
        const float* wr = W_ih + j        * 80 + 16;
        const float* wz = W_ih + (32 + j) * 80 + 16;
        const float* wn = W_ih + (64 + j) * 80 + 16;
        #pragma unroll 8
        for (int k2 = 0; k2 < 64; ++k2) {
            float c = ctxa[k2];
            gir += wr[k2] * c;
            giz += wz[k2] * c;
            gin += wn[k2] * c;
        }
        float r = sigm(gir + gh_sm[j]);
        float z = sigm(giz + gh_sm[32 + j]);
        float n = tanhf(gin + r * gh_sm[64 + j]);
        float h = (1.f - z) * n + z * s_sm[j];
        if (write_h) out[BB + b * 32 + j] = h;

        float contrib = h * W_fc[j]
                      + ctxa[2 * j]     * W_fc[32 + 2 * j]
                      + ctxa[2 * j + 1] * W_fc[33 + 2 * j];
        if (j < 16) contrib += emb_sm[j] * W_fc[96 + j];
        #pragma unroll
        for (int off = 16; off > 0; off >>= 1)
            contrib += __shfl_xor_sync(0xffffffffu, contrib, off);
        if (j == 0) out[b] = contrib + b_fc[0];
    }
}

extern "C" void kernel_launch(void* const* d_in, const int* in_sizes, int n_in,
                              void* d_out, int out_size) {
    const float* dec_in = (const float*)d_in[0];
    const float* s_in   = (const float*)d_in[1];
    const float* enc    = (const float*)d_in[2];
    const float* W_attn = (const float*)d_in[3];
    const float* b_attn = (const float*)d_in[4];
    const float* v_attn = (const float*)d_in[5];
    const float* W_emb  = (const float*)d_in[6];
    const float* b_emb  = (const float*)d_in[7];
    const float* W_ih   = (const float*)d_in[8];
    const float* W_hh   = (const float*)d_in[9];
    const float* b_ih   = (const float*)d_in[10];
    const float* b_hh   = (const float*)d_in[11];
    const float* W_fc   = (const float*)d_in[12];
    const float* b_fc   = (const float*)d_in[13];

    cudaFuncSetAttribute(decoder_deep_kernel,
                         cudaFuncAttributeMaxDynamicSharedMemorySize, SMEM_SZ);
    int write_h = (out_size >= BB * 33) ? 1 : 0;
    decoder_deep_kernel<<<BB, 256, SMEM_SZ>>>(dec_in, s_in, enc, W_attn, b_attn, v_attn,
                                              W_emb, b_emb, W_ih, W_hh, b_ih, b_hh,
                                              W_fc, b_fc, (float*)d_out, write_h);
}